// round 13
// baseline (speedup 1.0000x reference)
#include <cuda_runtime.h>
#include <cuda_fp16.h>
#include <math.h>
#include <stdint.h>

// ============================================================================
// HolomorphicEqProp — round 13: round-12 + fine-grained per-tile dependency
// flags in the persistent step kernel (per-K-chunk waits, rotated chunk order)
// ============================================================================

#define H_DIM   1024
#define B_DIM   4096
#define NSTEPS  30

__device__ __forceinline__ uint32_t smem_u32(const void* p) {
    uint32_t a;
    asm("{ .reg .u64 t; cvta.to.shared.u64 t, %1; cvt.u32.u64 %0, t; }" : "=r"(a) : "l"(p));
    return a;
}
__device__ __forceinline__ void cp_async16(uint32_t saddr, const void* g) {
    asm volatile("cp.async.cg.shared.global [%0], [%1], 16;" :: "r"(saddr), "l"(g));
}
#define CP_COMMIT() asm volatile("cp.async.commit_group;" ::: "memory")
#define CP_WAIT(n)  asm volatile("cp.async.wait_group %0;" :: "n"(n) : "memory")

__device__ __forceinline__ void ldm_x4(uint32_t* r, uint32_t addr) {
    asm volatile("ldmatrix.sync.aligned.m8n8.x4.shared.b16 {%0,%1,%2,%3}, [%4];"
                 : "=r"(r[0]), "=r"(r[1]), "=r"(r[2]), "=r"(r[3]) : "r"(addr));
}
__device__ __forceinline__ void mma16816(float* c, const uint32_t* a, uint32_t b0, uint32_t b1) {
    asm volatile("mma.sync.aligned.m16n8k16.row.col.f32.f16.f16.f32 "
                 "{%0,%1,%2,%3}, {%4,%5,%6,%7}, {%8,%9}, {%0,%1,%2,%3};"
                 : "+f"(c[0]), "+f"(c[1]), "+f"(c[2]), "+f"(c[3])
                 : "r"(a[0]), "r"(a[1]), "r"(a[2]), "r"(a[3]), "r"(b0), "r"(b1));
}
__device__ __forceinline__ uint32_t h2_scale_dn(uint32_t x) {   // * 2^-11 packed
    uint32_t r;
    asm("mul.f16x2 %0, %1, %2;" : "=r"(r) : "r"(x), "r"(0x10001000u));
    return r;
}
__device__ __forceinline__ uint32_t swz(int row, int seg) {
    uint32_t o = ((uint32_t)row << 7) | ((uint32_t)seg << 4);
    return o ^ ((o >> 3) & 0x70);
}
__device__ __forceinline__ void wait_acq(const int* p) {
    int v;
    for (;;) {
        asm volatile("ld.acquire.gpu.s32 %0, [%1];" : "=r"(v) : "l"(p) : "memory");
        if (v) return;
        __nanosleep(32);
    }
}
__device__ __forceinline__ void st_rel(int* p, int v) {
    asm volatile("st.release.gpu.s32 [%0], %1;" :: "l"(p), "r"(v) : "memory");
}

// ---------------------------------------------------------------------------
// static scratch
// ---------------------------------------------------------------------------
__device__ __half g_xhi[B_DIM * H_DIM];
__device__ __half g_wih[H_DIM * H_DIM], g_wil[H_DIM * H_DIM];
__device__ __half g_wrh[H_DIM * H_DIM], g_wrl[H_DIM * H_DIM];
__device__ __half g_woh[256 * H_DIM],  g_wol[256 * H_DIM];
__device__ float  g_xproj[B_DIM * H_DIM];
__device__ __half g_h[2][B_DIM * H_DIM];
__device__ float  g_y[3 * H_DIM], g_v[3 * H_DIM], g_z[3 * H_DIM], g_invsig[3];
__device__ int    g_flag[NSTEPS * 256];

// ---------------------------------------------------------------------------
// merged prologue kernels
// ---------------------------------------------------------------------------
__device__ __forceinline__ float block_reduce_sum(float v) {
    __shared__ float sh[32];
    int lane = threadIdx.x & 31, w = threadIdx.x >> 5;
    #pragma unroll
    for (int o = 16; o; o >>= 1) v += __shfl_xor_sync(0xffffffffu, v, o);
    if (!lane) sh[w] = v;
    __syncthreads();
    int nw = blockDim.x >> 5;
    v = (threadIdx.x < nw) ? sh[threadIdx.x] : 0.0f;
    if (w == 0) {
        #pragma unroll
        for (int o = 16; o; o >>= 1) v += __shfl_xor_sync(0xffffffffu, v, o);
        if (!lane) sh[0] = v;
    }
    __syncthreads();
    return sh[0];
}

__global__ void zero_all(float* y, int ny, int* flg, int nc) {
    int i = blockIdx.x * blockDim.x + threadIdx.x;
    if (i < ny) y[i] = 0.0f;
    if (i < nc) flg[i] = 0;
}

__global__ void colmv_all(const float* __restrict__ Wi, const float* __restrict__ ui,
                          const float* __restrict__ Wr, const float* __restrict__ ur,
                          const float* __restrict__ Wo, const float* __restrict__ uo,
                          float* __restrict__ y, int DIN, int H, int DOUT) {
    const int mat = blockIdx.z;
    const float* W; const float* u; int R, C;
    if (mat == 0)      { W = Wi; u = ui; R = H;    C = DIN; }
    else if (mat == 1) { W = Wr; u = ur; R = H;    C = H;   }
    else               { W = Wo; u = uo; R = DOUT; C = H;   }
    int c = blockIdx.x * blockDim.x + threadIdx.x;
    if (c >= C) return;
    int per = R / gridDim.y;
    int r0 = blockIdx.y * per;
    int r1 = (blockIdx.y == gridDim.y - 1) ? R : r0 + per;
    float acc = 0.0f;
    for (int r = r0; r < r1; r++) acc += W[(long)r * C + c] * u[r];
    atomicAdd(&y[mat * H_DIM + c], acc);
}

__global__ void normalize_all(const float* __restrict__ y, float* __restrict__ v,
                              int DIN, int H) {
    const int mat = blockIdx.x;
    const int n = (mat == 0) ? DIN : H;
    const float* ym = y + mat * H_DIM;
    float* vm = v + mat * H_DIM;
    float ss = 0.0f;
    for (int i = threadIdx.x; i < n; i += blockDim.x) { float t = ym[i]; ss += t * t; }
    float tot = block_reduce_sum(ss);
    float scale = 1.0f / (sqrtf(tot) + 1e-12f);
    for (int i = threadIdx.x; i < n; i += blockDim.x) vm[i] = ym[i] * scale;
}

__global__ void rowmv_all(const float* __restrict__ Wi, const float* __restrict__ Wr,
                          const float* __restrict__ Wo, const float* __restrict__ v,
                          float* __restrict__ z, int DIN, int H, int DOUT) {
    const int mat = blockIdx.y;
    const float* W; int R, C;
    if (mat == 0)      { W = Wi; R = H;    C = DIN; }
    else if (mat == 1) { W = Wr; R = H;    C = H;   }
    else               { W = Wo; R = DOUT; C = H;   }
    int warp = (blockIdx.x * blockDim.x + threadIdx.x) >> 5;
    int lane = threadIdx.x & 31;
    if (warp >= R) return;
    const float* vm = v + mat * H_DIM;
    float acc = 0.0f;
    for (int c = lane; c < C; c += 32) acc += W[(long)warp * C + c] * vm[c];
    #pragma unroll
    for (int o = 16; o; o >>= 1) acc += __shfl_xor_sync(0xffffffffu, acc, o);
    if (!lane) z[mat * H_DIM + warp] = acc;
}

__global__ void sigma_all(const float* __restrict__ z, float* __restrict__ invsig,
                          int H, int DOUT) {
    const int mat = blockIdx.x;
    const int n = (mat == 2) ? DOUT : H;
    const float* zm = z + mat * H_DIM;
    float ss = 0.0f;
    for (int i = threadIdx.x; i < n; i += blockDim.x) { float t = zm[i]; ss += t * t; }
    float tot = block_reduce_sum(ss);
    if (threadIdx.x == 0) {
        float nz = sqrtf(tot);
        invsig[mat] = (nz + 1e-12f) / tot;
    }
}

// one launch: x -> hi only; weights -> hi/lo Ootomo split
__global__ void split_all(const float* __restrict__ x, const float* __restrict__ Wi,
                          const float* __restrict__ Wr, const float* __restrict__ Wo,
                          long nx, long nwi, long nwr, long nwo) {
    long i = (long)blockIdx.x * blockDim.x + threadIdx.x;
    const float* s; __half* hi; __half* lo; long j = i;
    if (j < nx)               { s = x;  hi = g_xhi; lo = nullptr; }
    else if ((j -= nx) < nwi) { s = Wi; hi = g_wih; lo = g_wil; }
    else if ((j -= nwi) < nwr){ s = Wr; hi = g_wrh; lo = g_wrl; }
    else if ((j -= nwr) < nwo){ s = Wo; hi = g_woh; lo = g_wol; }
    else return;
    float f = s[j];
    __half h = __float2half_rn(f);
    hi[j] = h;
    if (lo) lo[j] = __float2half_rn((f - __half2float(h)) * 2048.0f);
}

// ---------------------------------------------------------------------------
// fused GEMM, A plain fp16, B 2-term (Bhi + 2^-11 Blo'): used for xproj & out
// ---------------------------------------------------------------------------
__global__ __launch_bounds__(256, 2)
void mma_gemm_b2(const __half* __restrict__ A1,
                 const __half* __restrict__ B1, const __half* __restrict__ B2,
                 const float* __restrict__ bias, const float* __restrict__ invsig,
                 int K, int N, float* __restrict__ Cf32) {
    constexpr int MAT_B = 16384;
    constexpr int STAGE_B = 3 * MAT_B;     // 48KB, 2 stages = 96KB

    extern __shared__ char sm[];
    const uint32_t sbase = smem_u32(sm);
    const int tid = threadIdx.x, wid = tid >> 5, lane = tid & 31;
    const int bm = blockIdx.y * 128, bn = blockIdx.x * 128;
    const int wm = (wid >> 2) * 64, wn = (wid & 3) * 32;

    const __half* src[3];
    src[0] = A1 + (size_t)bm * K;
    src[1] = B1 + (size_t)bn * K;
    src[2] = B2 + (size_t)bn * K;

    float acc[4][4][4];
    #pragma unroll
    for (int mi = 0; mi < 4; mi++)
        #pragma unroll
        for (int ni = 0; ni < 4; ni++)
            #pragma unroll
            for (int k = 0; k < 4; k++) acc[mi][ni][k] = 0.0f;

    auto stage_load = [&](int chunk, int buf) {
        const uint32_t sb = sbase + buf * STAGE_B;
        const int k0 = chunk << 6;
        #pragma unroll
        for (int it = 0; it < 12; it++) {
            const int flat = it * 256 + tid;
            const int m = flat >> 10;
            const int rem = flat & 1023;
            const int row = rem >> 3, seg = rem & 7;
            cp_async16(sb + m * MAT_B + swz(row, seg),
                       src[m] + (size_t)row * K + k0 + seg * 8);
        }
    };

    const int nch = K >> 6;
    stage_load(0, 0);
    CP_COMMIT();

    for (int c = 0; c < nch; c++) {
        if (c + 1 < nch) { stage_load(c + 1, (c + 1) & 1); CP_COMMIT(); CP_WAIT(1); }
        else             { CP_WAIT(0); }
        __syncthreads();

        const uint32_t sa = sbase + (c & 1) * STAGE_B;
        #pragma unroll
        for (int ks = 0; ks < 4; ks++) {
            const int seg = ks * 2 + (lane >> 4);
            uint32_t af[4][4], b1[2][4], b2f[2][4];
            #pragma unroll
            for (int mi = 0; mi < 4; mi++)
                ldm_x4(af[mi], sa + swz(wm + mi * 16 + (lane & 15), seg));
            #pragma unroll
            for (int nb = 0; nb < 2; nb++) {
                ldm_x4(b1[nb],  sa + MAT_B     + swz(wn + nb * 16 + (lane & 15), seg));
                ldm_x4(b2f[nb], sa + 2 * MAT_B + swz(wn + nb * 16 + (lane & 15), seg));
            }
            #pragma unroll
            for (int mi = 0; mi < 4; mi++)
                #pragma unroll
                for (int ni = 0; ni < 4; ni++)
                    mma16816(acc[mi][ni], af[mi],
                             b1[ni >> 1][ni & 1], b1[ni >> 1][(ni & 1) + 2]);
            #pragma unroll
            for (int mi = 0; mi < 4; mi++)
                #pragma unroll
                for (int r = 0; r < 4; r++) af[mi][r] = h2_scale_dn(af[mi][r]);
            #pragma unroll
            for (int mi = 0; mi < 4; mi++)
                #pragma unroll
                for (int ni = 0; ni < 4; ni++)
                    mma16816(acc[mi][ni], af[mi],
                             b2f[ni >> 1][ni & 1], b2f[ni >> 1][(ni & 1) + 2]);
        }
        __syncthreads();
    }

    const float sig = *invsig;
    const int quad = lane >> 2, tq = lane & 3;
    #pragma unroll
    for (int mi = 0; mi < 4; mi++)
        #pragma unroll
        for (int ni = 0; ni < 4; ni++) {
            const int col = bn + wn + ni * 8 + tq * 2;
            const float b0 = bias[col], b1v = bias[col + 1];
            #pragma unroll
            for (int hr = 0; hr < 2; hr++) {
                const int row = bm + wm + mi * 16 + quad + hr * 8;
                const size_t idx = (size_t)row * N + col;
                float2 o;
                o.x = acc[mi][ni][hr * 2 + 0] * sig + b0;
                o.y = acc[mi][ni][hr * 2 + 1] * sig + b1v;
                *(float2*)(Cf32 + idx) = o;
            }
        }
}

// ---------------------------------------------------------------------------
// persistent 30-step kernel, grid (8, 32); per-tile flags, per-chunk waits,
// chunk order rotated by 2*bnb so consumers start on distinct producers.
// ---------------------------------------------------------------------------
__global__ __launch_bounds__(256, 2)
void step_persistent(__half* __restrict__ hb0, __half* __restrict__ hb1,
                     const __half* __restrict__ W, const float* __restrict__ brec,
                     const float* __restrict__ invsig, const float* __restrict__ xproj,
                     const int* __restrict__ steps, int* __restrict__ flag) {
    constexpr int MAT_B = 16384;
    constexpr int STAGE_B = 2 * MAT_B;
    extern __shared__ char sm[];
    const uint32_t sbase = smem_u32(sm);

    const int tid = threadIdx.x, wid = tid >> 5, lane = tid & 31;
    const int bnb = blockIdx.x, bmb = blockIdx.y;
    const int bm = bmb * 128, bn = bnb * 128;
    const int wm = (wid >> 2) * 64, wn = (wid & 3) * 32;
    const int st = *steps;
    const float sig = *invsig;
    const int rot = bnb << 1;                 // chunk rotation (2 chunks/col-block)

    // ---- t = 0: h0 tile = tanh(xproj + brec) (mod0 = 1)
    {
        #pragma unroll
        for (int i = 0; i < 32; i++) {
            const int p = i * 256 + tid;
            const int row = p >> 6, col = (p & 63) * 2;
            const size_t idx = (size_t)(bm + row) * H_DIM + bn + col;
            const float2 xp = *(const float2*)(xproj + idx);
            const float2 bb = *(const float2*)(brec + bn + col);
            union { __half h[2]; uint32_t u; } ph;
            if (0 < st) {
                ph.h[0] = __float2half_rn(tanhf(xp.x + bb.x));
                ph.h[1] = __float2half_rn(tanhf(xp.y + bb.y));
            } else {
                ph.h[0] = __float2half_rn(0.0f);
                ph.h[1] = __float2half_rn(0.0f);
            }
            *(uint32_t*)(hb0 + idx) = ph.u;
        }
        __syncthreads();
        if (tid == 0) st_rel(&flag[(bmb << 3) + bnb], 1);
    }

    const __half* Bptr = W + (size_t)bn * H_DIM;

    for (int t = 1; t < NSTEPS; t++) {
        const __half* src = ((t & 1) ? hb0 : hb1) + (size_t)bm * H_DIM;
        __half* dst = (t & 1) ? hb1 : hb0;
        const float mod = 1.0f + 0.1f * sinf(0.3f * (float)t);
        const int* fbase = flag + (t - 1) * 256 + (bmb << 3);

        float acc[4][4][4];
        #pragma unroll
        for (int mi = 0; mi < 4; mi++)
            #pragma unroll
            for (int ni = 0; ni < 4; ni++)
                #pragma unroll
                for (int k = 0; k < 4; k++) acc[mi][ni][k] = 0.0f;

        auto stage_load = [&](int chunk, int buf) {
            const uint32_t sb = sbase + buf * STAGE_B;
            const int k0 = chunk << 6;
            #pragma unroll
            for (int it = 0; it < 8; it++) {
                const int flat = it * 256 + tid;
                const int m = flat >> 10;
                const int rem = flat & 1023;
                const int row = rem >> 3, seg = rem & 7;
                const __half* s = m ? Bptr : src;
                cp_async16(sb + m * MAT_B + swz(row, seg),
                           s + (size_t)row * H_DIM + k0 + seg * 8);
            }
        };

        // prologue: chunks phys(0..1) belong to col-block bnb
        if (tid == 0) wait_acq(fbase + bnb);
        __syncthreads();
        stage_load(rot, 0);              CP_COMMIT();
        stage_load((rot + 1) & 15, 1);   CP_COMMIT();

        #pragma unroll 1
        for (int c = 0; c < 16; c++) {
            if (c < 15) { CP_WAIT(1); } else { CP_WAIT(0); }
            if (tid == 0 && (c & 1) == 0 && c + 2 < 16)
                wait_acq(fbase + (((c + 2 + rot) & 15) >> 1));
            __syncthreads();
            if (c + 2 < 16) { stage_load((c + 2 + rot) & 15, (c + 2) % 3); CP_COMMIT(); }

            const uint32_t sa = sbase + (c % 3) * STAGE_B;
            #pragma unroll
            for (int ks = 0; ks < 4; ks++) {
                const int seg = ks * 2 + (lane >> 4);
                uint32_t af[4][4], b1[2][4];
                #pragma unroll
                for (int mi = 0; mi < 4; mi++)
                    ldm_x4(af[mi], sa + swz(wm + mi * 16 + (lane & 15), seg));
                #pragma unroll
                for (int nb = 0; nb < 2; nb++)
                    ldm_x4(b1[nb], sa + MAT_B + swz(wn + nb * 16 + (lane & 15), seg));
                #pragma unroll
                for (int mi = 0; mi < 4; mi++)
                    #pragma unroll
                    for (int ni = 0; ni < 4; ni++)
                        mma16816(acc[mi][ni], af[mi],
                                 b1[ni >> 1][ni & 1], b1[ni >> 1][(ni & 1) + 2]);
            }
        }

        const int quad = lane >> 2, tq = lane & 3;
        #pragma unroll
        for (int mi = 0; mi < 4; mi++)
            #pragma unroll
            for (int ni = 0; ni < 4; ni++) {
                const int col = bn + wn + ni * 8 + tq * 2;
                const float b0 = brec[col], b1v = brec[col + 1];
                #pragma unroll
                for (int hr = 0; hr < 2; hr++) {
                    const int row = bm + wm + mi * 16 + quad + hr * 8;
                    const size_t idx = (size_t)row * H_DIM + col;
                    if (t < st) {
                        const float2 xp = *(const float2*)(xproj + idx);
                        const float v0 = acc[mi][ni][hr * 2] * sig + b0;
                        const float v1 = acc[mi][ni][hr * 2 + 1] * sig + b1v;
                        union { __half h[2]; uint32_t u; } ph;
                        ph.h[0] = __float2half_rn(tanhf(xp.x + v0 * mod));
                        ph.h[1] = __float2half_rn(tanhf(xp.y + v1 * mod));
                        *(uint32_t*)(dst + idx) = ph.u;
                    } else {
                        *(uint32_t*)(dst + idx) =
                            *(const uint32_t*)(src + (size_t)(row - bm) * H_DIM + col);
                    }
                }
            }

        __syncthreads();
        if (tid == 0) st_rel(&flag[t * 256 + (bmb << 3) + bnb], 1);
    }
}

// ---------------------------------------------------------------------------
// launch
// ---------------------------------------------------------------------------
extern "C" void kernel_launch(void* const* d_in, const int* in_sizes, int n_in,
                              void* d_out, int out_size) {
    const float* x     = (const float*)d_in[0];
    const float* W_in  = (const float*)d_in[1];
    const float* b_in  = (const float*)d_in[2];
    const float* W_rec = (const float*)d_in[3];
    const float* b_rec = (const float*)d_in[4];
    const float* W_out = (const float*)d_in[5];
    const float* b_out = (const float*)d_in[6];
    const float* u_in  = (const float*)d_in[7];
    const float* u_rec = (const float*)d_in[8];
    const float* u_out = (const float*)d_in[9];
    const int*   steps = (const int*)d_in[10];

    const int H    = in_sizes[2];
    const int DIN  = in_sizes[1] / H;
    const int B    = in_sizes[0] / DIN;
    const int DOUT = in_sizes[6];

    __half *xhi, *wih, *wil, *wrh, *woh, *wol, *hbuf0;
    float *xproj, *y, *v, *z, *invsig;
    int* flg;
    cudaGetSymbolAddress((void**)&xhi, g_xhi);
    cudaGetSymbolAddress((void**)&wih, g_wih);   cudaGetSymbolAddress((void**)&wil, g_wil);
    cudaGetSymbolAddress((void**)&wrh, g_wrh);
    cudaGetSymbolAddress((void**)&woh, g_woh);   cudaGetSymbolAddress((void**)&wol, g_wol);
    cudaGetSymbolAddress((void**)&hbuf0, g_h);
    cudaGetSymbolAddress((void**)&xproj, g_xproj);
    cudaGetSymbolAddress((void**)&y, g_y); cudaGetSymbolAddress((void**)&v, g_v);
    cudaGetSymbolAddress((void**)&z, g_z); cudaGetSymbolAddress((void**)&invsig, g_invsig);
    cudaGetSymbolAddress((void**)&flg, g_flag);

    __half* hb0 = hbuf0;
    __half* hb1 = hbuf0 + (long)B_DIM * H_DIM;

    constexpr int SMEM_STEP = 3 * 2 * 16384;   // 96KB
    constexpr int SMEM_B2   = 2 * 3 * 16384;   // 96KB
    cudaFuncSetAttribute(step_persistent, cudaFuncAttributeMaxDynamicSharedMemorySize, SMEM_STEP);
    cudaFuncSetAttribute(mma_gemm_b2,     cudaFuncAttributeMaxDynamicSharedMemorySize, SMEM_B2);

    // merged prologue: 6 launches
    zero_all<<<(NSTEPS * 256 + 255) / 256, 256>>>(y, 3 * H_DIM, flg, NSTEPS * 256);
    colmv_all<<<dim3((H_DIM + 127) / 128, 8, 3), 128>>>(W_in, u_in, W_rec, u_rec,
                                                        W_out, u_out, y, DIN, H, DOUT);
    normalize_all<<<3, 256>>>(y, v, DIN, H);
    rowmv_all<<<dim3((H_DIM + 7) / 8, 3), 256>>>(W_in, W_rec, W_out, v, z, DIN, H, DOUT);
    sigma_all<<<3, 256>>>(z, invsig, H, DOUT);
    {
        long nx = (long)B * DIN, nwi = (long)H * DIN, nwr = (long)H * H, nwo = (long)DOUT * H;
        long tot = nx + nwi + nwr + nwo;
        split_all<<<(int)((tot + 255) / 256), 256>>>(x, W_in, W_rec, W_out, nx, nwi, nwr, nwo);
    }

    // x_proj = x @ (W_in/s)^T + b_in   (2-term: x plain fp16, W weight-exact)
    mma_gemm_b2<<<dim3(H / 128, B / 128), 256, SMEM_B2>>>(
        xhi, wih, wil, b_in, invsig + 0, DIN, H, xproj);

    // persistent: h0 init + steps 1..29
    step_persistent<<<dim3(H / 128, B / 128), 256, SMEM_STEP>>>(
        hb0, hb1, wrh, b_rec, invsig + 1, xproj, steps, flg);

    // out = h @ (W_out/s)^T + b_out   (2-term); final h in hb1 (NSTEPS-1 odd)
    mma_gemm_b2<<<dim3(DOUT / 128, B / 128), 256, SMEM_B2>>>(
        hb1, woh, wol, b_out, invsig + 2, H, DOUT, (float*)d_out);
}

// round 14
// speedup vs baseline: 1.1011x; 1.1011x over previous
#include <cuda_runtime.h>
#include <cuda_fp16.h>
#include <math.h>
#include <stdint.h>

// ============================================================================
// HolomorphicEqProp — round 14: R12 skeleton; ALL GEMMs single-MMA plain fp16
// (weights quantized; error budget calibrated over rounds 4-12)
// ============================================================================

#define H_DIM   1024
#define B_DIM   4096
#define NSTEPS  30

__device__ __forceinline__ uint32_t smem_u32(const void* p) {
    uint32_t a;
    asm("{ .reg .u64 t; cvta.to.shared.u64 t, %1; cvt.u32.u64 %0, t; }" : "=r"(a) : "l"(p));
    return a;
}
__device__ __forceinline__ void cp_async16(uint32_t saddr, const void* g) {
    asm volatile("cp.async.cg.shared.global [%0], [%1], 16;" :: "r"(saddr), "l"(g));
}
#define CP_COMMIT() asm volatile("cp.async.commit_group;" ::: "memory")
#define CP_WAIT(n)  asm volatile("cp.async.wait_group %0;" :: "n"(n) : "memory")

__device__ __forceinline__ void ldm_x4(uint32_t* r, uint32_t addr) {
    asm volatile("ldmatrix.sync.aligned.m8n8.x4.shared.b16 {%0,%1,%2,%3}, [%4];"
                 : "=r"(r[0]), "=r"(r[1]), "=r"(r[2]), "=r"(r[3]) : "r"(addr));
}
__device__ __forceinline__ void mma16816(float* c, const uint32_t* a, uint32_t b0, uint32_t b1) {
    asm volatile("mma.sync.aligned.m16n8k16.row.col.f32.f16.f16.f32 "
                 "{%0,%1,%2,%3}, {%4,%5,%6,%7}, {%8,%9}, {%0,%1,%2,%3};"
                 : "+f"(c[0]), "+f"(c[1]), "+f"(c[2]), "+f"(c[3])
                 : "r"(a[0]), "r"(a[1]), "r"(a[2]), "r"(a[3]), "r"(b0), "r"(b1));
}
__device__ __forceinline__ uint32_t swz(int row, int seg) {
    uint32_t o = ((uint32_t)row << 7) | ((uint32_t)seg << 4);
    return o ^ ((o >> 3) & 0x70);
}
__device__ __forceinline__ int ld_relaxed(const int* p) {
    int v;
    asm volatile("ld.relaxed.gpu.s32 %0, [%1];" : "=r"(v) : "l"(p));
    return v;
}

// ---------------------------------------------------------------------------
// static scratch
// ---------------------------------------------------------------------------
__device__ __half g_xhi[B_DIM * H_DIM];
__device__ __half g_wih[H_DIM * H_DIM];
__device__ __half g_wrh[H_DIM * H_DIM];
__device__ __half g_woh[256 * H_DIM];
__device__ float  g_xproj[B_DIM * H_DIM];
__device__ __half g_h[2][B_DIM * H_DIM];
__device__ float  g_y[3 * H_DIM], g_v[3 * H_DIM], g_z[3 * H_DIM], g_invsig[3];
__device__ int    g_cnt[NSTEPS * 32];

// ---------------------------------------------------------------------------
// merged prologue kernels
// ---------------------------------------------------------------------------
__device__ __forceinline__ float block_reduce_sum(float v) {
    __shared__ float sh[32];
    int lane = threadIdx.x & 31, w = threadIdx.x >> 5;
    #pragma unroll
    for (int o = 16; o; o >>= 1) v += __shfl_xor_sync(0xffffffffu, v, o);
    if (!lane) sh[w] = v;
    __syncthreads();
    int nw = blockDim.x >> 5;
    v = (threadIdx.x < nw) ? sh[threadIdx.x] : 0.0f;
    if (w == 0) {
        #pragma unroll
        for (int o = 16; o; o >>= 1) v += __shfl_xor_sync(0xffffffffu, v, o);
        if (!lane) sh[0] = v;
    }
    __syncthreads();
    return sh[0];
}

__global__ void zero_all(float* y, int ny, int* cnt, int nc) {
    int i = blockIdx.x * blockDim.x + threadIdx.x;
    if (i < ny) y[i] = 0.0f;
    if (i < nc) cnt[i] = 0;
}

__global__ void colmv_all(const float* __restrict__ Wi, const float* __restrict__ ui,
                          const float* __restrict__ Wr, const float* __restrict__ ur,
                          const float* __restrict__ Wo, const float* __restrict__ uo,
                          float* __restrict__ y, int DIN, int H, int DOUT) {
    const int mat = blockIdx.z;
    const float* W; const float* u; int R, C;
    if (mat == 0)      { W = Wi; u = ui; R = H;    C = DIN; }
    else if (mat == 1) { W = Wr; u = ur; R = H;    C = H;   }
    else               { W = Wo; u = uo; R = DOUT; C = H;   }
    int c = blockIdx.x * blockDim.x + threadIdx.x;
    if (c >= C) return;
    int per = R / gridDim.y;
    int r0 = blockIdx.y * per;
    int r1 = (blockIdx.y == gridDim.y - 1) ? R : r0 + per;
    float acc = 0.0f;
    for (int r = r0; r < r1; r++) acc += W[(long)r * C + c] * u[r];
    atomicAdd(&y[mat * H_DIM + c], acc);
}

__global__ void normalize_all(const float* __restrict__ y, float* __restrict__ v,
                              int DIN, int H) {
    const int mat = blockIdx.x;
    const int n = (mat == 0) ? DIN : H;
    const float* ym = y + mat * H_DIM;
    float* vm = v + mat * H_DIM;
    float ss = 0.0f;
    for (int i = threadIdx.x; i < n; i += blockDim.x) { float t = ym[i]; ss += t * t; }
    float tot = block_reduce_sum(ss);
    float scale = 1.0f / (sqrtf(tot) + 1e-12f);
    for (int i = threadIdx.x; i < n; i += blockDim.x) vm[i] = ym[i] * scale;
}

__global__ void rowmv_all(const float* __restrict__ Wi, const float* __restrict__ Wr,
                          const float* __restrict__ Wo, const float* __restrict__ v,
                          float* __restrict__ z, int DIN, int H, int DOUT) {
    const int mat = blockIdx.y;
    const float* W; int R, C;
    if (mat == 0)      { W = Wi; R = H;    C = DIN; }
    else if (mat == 1) { W = Wr; R = H;    C = H;   }
    else               { W = Wo; R = DOUT; C = H;   }
    int warp = (blockIdx.x * blockDim.x + threadIdx.x) >> 5;
    int lane = threadIdx.x & 31;
    if (warp >= R) return;
    const float* vm = v + mat * H_DIM;
    float acc = 0.0f;
    for (int c = lane; c < C; c += 32) acc += W[(long)warp * C + c] * vm[c];
    #pragma unroll
    for (int o = 16; o; o >>= 1) acc += __shfl_xor_sync(0xffffffffu, acc, o);
    if (!lane) z[mat * H_DIM + warp] = acc;
}

__global__ void sigma_all(const float* __restrict__ z, float* __restrict__ invsig,
                          int H, int DOUT) {
    const int mat = blockIdx.x;
    const int n = (mat == 2) ? DOUT : H;
    const float* zm = z + mat * H_DIM;
    float ss = 0.0f;
    for (int i = threadIdx.x; i < n; i += blockDim.x) { float t = zm[i]; ss += t * t; }
    float tot = block_reduce_sum(ss);
    if (threadIdx.x == 0) {
        float nz = sqrtf(tot);
        invsig[mat] = (nz + 1e-12f) / tot;
    }
}

// one launch: all four tensors -> plain fp16
__global__ void split_all(const float* __restrict__ x, const float* __restrict__ Wi,
                          const float* __restrict__ Wr, const float* __restrict__ Wo,
                          long nx, long nwi, long nwr, long nwo) {
    long i = (long)blockIdx.x * blockDim.x + threadIdx.x;
    const float* s; __half* hi; long j = i;
    if (j < nx)               { s = x;  hi = g_xhi; }
    else if ((j -= nx) < nwi) { s = Wi; hi = g_wih; }
    else if ((j -= nwi) < nwr){ s = Wr; hi = g_wrh; }
    else if ((j -= nwr) < nwo){ s = Wo; hi = g_woh; }
    else return;
    hi[j] = __float2half_rn(s[j]);
}

// ---------------------------------------------------------------------------
// plain fp16 GEMM (A, B both fp16; single MMA), 2 mats/stage, 3-stage, 96KB
//   C = acc * invsig + bias   (fp32 out) — used for xproj and out GEMMs
// ---------------------------------------------------------------------------
__global__ __launch_bounds__(256, 2)
void mma_gemm_p(const __half* __restrict__ A1, const __half* __restrict__ B1,
                const float* __restrict__ bias, const float* __restrict__ invsig,
                int K, int N, float* __restrict__ Cf32) {
    constexpr int MAT_B = 16384;
    constexpr int STAGE_B = 2 * MAT_B;

    extern __shared__ char sm[];
    const uint32_t sbase = smem_u32(sm);
    const int tid = threadIdx.x, wid = tid >> 5, lane = tid & 31;
    const int bm = blockIdx.y * 128, bn = blockIdx.x * 128;
    const int wm = (wid >> 2) * 64, wn = (wid & 3) * 32;

    const __half* srcA = A1 + (size_t)bm * K;
    const __half* srcB = B1 + (size_t)bn * K;

    float acc[4][4][4];
    #pragma unroll
    for (int mi = 0; mi < 4; mi++)
        #pragma unroll
        for (int ni = 0; ni < 4; ni++)
            #pragma unroll
            for (int k = 0; k < 4; k++) acc[mi][ni][k] = 0.0f;

    auto stage_load = [&](int chunk, int buf) {
        const uint32_t sb = sbase + buf * STAGE_B;
        const int k0 = chunk << 6;
        #pragma unroll
        for (int it = 0; it < 8; it++) {
            const int flat = it * 256 + tid;
            const int m = flat >> 10;
            const int rem = flat & 1023;
            const int row = rem >> 3, seg = rem & 7;
            const __half* s = m ? srcB : srcA;
            cp_async16(sb + m * MAT_B + swz(row, seg),
                       s + (size_t)row * K + k0 + seg * 8);
        }
    };

    const int nch = K >> 6;
    stage_load(0, 0); CP_COMMIT();
    stage_load(1, 1); CP_COMMIT();

    #pragma unroll 1
    for (int c = 0; c < nch; c++) {
        if (c + 1 < nch) { CP_WAIT(1); } else { CP_WAIT(0); }
        __syncthreads();
        if (c + 2 < nch) { stage_load(c + 2, (c + 2) % 3); CP_COMMIT(); }

        const uint32_t sa = sbase + (c % 3) * STAGE_B;
        #pragma unroll
        for (int ks = 0; ks < 4; ks++) {
            const int seg = ks * 2 + (lane >> 4);
            uint32_t af[4][4], b1[2][4];
            #pragma unroll
            for (int mi = 0; mi < 4; mi++)
                ldm_x4(af[mi], sa + swz(wm + mi * 16 + (lane & 15), seg));
            #pragma unroll
            for (int nb = 0; nb < 2; nb++)
                ldm_x4(b1[nb], sa + MAT_B + swz(wn + nb * 16 + (lane & 15), seg));
            #pragma unroll
            for (int mi = 0; mi < 4; mi++)
                #pragma unroll
                for (int ni = 0; ni < 4; ni++)
                    mma16816(acc[mi][ni], af[mi],
                             b1[ni >> 1][ni & 1], b1[ni >> 1][(ni & 1) + 2]);
        }
    }

    const float sig = *invsig;
    const int quad = lane >> 2, tq = lane & 3;
    #pragma unroll
    for (int mi = 0; mi < 4; mi++)
        #pragma unroll
        for (int ni = 0; ni < 4; ni++) {
            const int col = bn + wn + ni * 8 + tq * 2;
            const float b0 = bias[col], b1v = bias[col + 1];
            #pragma unroll
            for (int hr = 0; hr < 2; hr++) {
                const int row = bm + wm + mi * 16 + quad + hr * 8;
                const size_t idx = (size_t)row * N + col;
                float2 o;
                o.x = acc[mi][ni][hr * 2 + 0] * sig + b0;
                o.y = acc[mi][ni][hr * 2 + 1] * sig + b1v;
                *(float2*)(Cf32 + idx) = o;
            }
        }
}

// ---------------------------------------------------------------------------
// persistent 30-step kernel (R12 exactly), grid (8, 32), single-sync 3-stage
// ---------------------------------------------------------------------------
__global__ __launch_bounds__(256, 2)
void step_persistent(__half* __restrict__ hb0, __half* __restrict__ hb1,
                     const __half* __restrict__ W, const float* __restrict__ brec,
                     const float* __restrict__ invsig, const float* __restrict__ xproj,
                     const int* __restrict__ steps, int* __restrict__ cnt) {
    constexpr int MAT_B = 16384;
    constexpr int STAGE_B = 2 * MAT_B;
    extern __shared__ char sm[];
    const uint32_t sbase = smem_u32(sm);

    const int tid = threadIdx.x, wid = tid >> 5, lane = tid & 31;
    const int bnb = blockIdx.x, bmb = blockIdx.y;
    const int bm = bmb * 128, bn = bnb * 128;
    const int wm = (wid >> 2) * 64, wn = (wid & 3) * 32;
    const int st = *steps;
    const float sig = *invsig;

    // ---- t = 0: h0 tile = tanh(xproj + brec) (mod0 = 1)
    {
        #pragma unroll
        for (int i = 0; i < 32; i++) {
            const int p = i * 256 + tid;
            const int row = p >> 6, col = (p & 63) * 2;
            const size_t idx = (size_t)(bm + row) * H_DIM + bn + col;
            const float2 xp = *(const float2*)(xproj + idx);
            const float2 bb = *(const float2*)(brec + bn + col);
            union { __half h[2]; uint32_t u; } ph;
            if (0 < st) {
                ph.h[0] = __float2half_rn(tanhf(xp.x + bb.x));
                ph.h[1] = __float2half_rn(tanhf(xp.y + bb.y));
            } else {
                ph.h[0] = __float2half_rn(0.0f);
                ph.h[1] = __float2half_rn(0.0f);
            }
            *(uint32_t*)(hb0 + idx) = ph.u;
        }
        __threadfence();
        __syncthreads();
        if (tid == 0) atomicAdd(&cnt[bmb], 1);
    }

    const __half* Bptr = W + (size_t)bn * H_DIM;

    for (int t = 1; t < NSTEPS; t++) {
        const __half* src = ((t & 1) ? hb0 : hb1) + (size_t)bm * H_DIM;
        __half* dst = (t & 1) ? hb1 : hb0;
        const float mod = 1.0f + 0.1f * sinf(0.3f * (float)t);

        if (tid == 0) {
            const int* c = &cnt[(t - 1) * 32 + bmb];
            while (ld_relaxed(c) < 8) __nanosleep(64);
        }
        __threadfence();
        __syncthreads();

        float acc[4][4][4];
        #pragma unroll
        for (int mi = 0; mi < 4; mi++)
            #pragma unroll
            for (int ni = 0; ni < 4; ni++)
                #pragma unroll
                for (int k = 0; k < 4; k++) acc[mi][ni][k] = 0.0f;

        auto stage_load = [&](int chunk, int buf) {
            const uint32_t sb = sbase + buf * STAGE_B;
            const int k0 = chunk << 6;
            #pragma unroll
            for (int it = 0; it < 8; it++) {
                const int flat = it * 256 + tid;
                const int m = flat >> 10;
                const int rem = flat & 1023;
                const int row = rem >> 3, seg = rem & 7;
                const __half* s = m ? Bptr : src;
                cp_async16(sb + m * MAT_B + swz(row, seg),
                           s + (size_t)row * H_DIM + k0 + seg * 8);
            }
        };

        stage_load(0, 0); CP_COMMIT();
        stage_load(1, 1); CP_COMMIT();

        #pragma unroll 1
        for (int c = 0; c < 16; c++) {
            if (c < 15) { CP_WAIT(1); } else { CP_WAIT(0); }
            __syncthreads();
            if (c + 2 < 16) { stage_load(c + 2, (c + 2) % 3); CP_COMMIT(); }

            const uint32_t sa = sbase + (c % 3) * STAGE_B;
            #pragma unroll
            for (int ks = 0; ks < 4; ks++) {
                const int seg = ks * 2 + (lane >> 4);
                uint32_t af[4][4], b1[2][4];
                #pragma unroll
                for (int mi = 0; mi < 4; mi++)
                    ldm_x4(af[mi], sa + swz(wm + mi * 16 + (lane & 15), seg));
                #pragma unroll
                for (int nb = 0; nb < 2; nb++)
                    ldm_x4(b1[nb], sa + MAT_B + swz(wn + nb * 16 + (lane & 15), seg));
                #pragma unroll
                for (int mi = 0; mi < 4; mi++)
                    #pragma unroll
                    for (int ni = 0; ni < 4; ni++)
                        mma16816(acc[mi][ni], af[mi],
                                 b1[ni >> 1][ni & 1], b1[ni >> 1][(ni & 1) + 2]);
            }
        }

        const int quad = lane >> 2, tq = lane & 3;
        #pragma unroll
        for (int mi = 0; mi < 4; mi++)
            #pragma unroll
            for (int ni = 0; ni < 4; ni++) {
                const int col = bn + wn + ni * 8 + tq * 2;
                const float b0 = brec[col], b1v = brec[col + 1];
                #pragma unroll
                for (int hr = 0; hr < 2; hr++) {
                    const int row = bm + wm + mi * 16 + quad + hr * 8;
                    const size_t idx = (size_t)row * H_DIM + col;
                    if (t < st) {
                        const float2 xp = *(const float2*)(xproj + idx);
                        const float v0 = acc[mi][ni][hr * 2] * sig + b0;
                        const float v1 = acc[mi][ni][hr * 2 + 1] * sig + b1v;
                        union { __half h[2]; uint32_t u; } ph;
                        ph.h[0] = __float2half_rn(tanhf(xp.x + v0 * mod));
                        ph.h[1] = __float2half_rn(tanhf(xp.y + v1 * mod));
                        *(uint32_t*)(dst + idx) = ph.u;
                    } else {
                        *(uint32_t*)(dst + idx) =
                            *(const uint32_t*)(src + (size_t)(row - bm) * H_DIM + col);
                    }
                }
            }

        __threadfence();
        __syncthreads();
        if (tid == 0) atomicAdd(&cnt[t * 32 + bmb], 1);
    }
}

// ---------------------------------------------------------------------------
// launch
// ---------------------------------------------------------------------------
extern "C" void kernel_launch(void* const* d_in, const int* in_sizes, int n_in,
                              void* d_out, int out_size) {
    const float* x     = (const float*)d_in[0];
    const float* W_in  = (const float*)d_in[1];
    const float* b_in  = (const float*)d_in[2];
    const float* W_rec = (const float*)d_in[3];
    const float* b_rec = (const float*)d_in[4];
    const float* W_out = (const float*)d_in[5];
    const float* b_out = (const float*)d_in[6];
    const float* u_in  = (const float*)d_in[7];
    const float* u_rec = (const float*)d_in[8];
    const float* u_out = (const float*)d_in[9];
    const int*   steps = (const int*)d_in[10];

    const int H    = in_sizes[2];
    const int DIN  = in_sizes[1] / H;
    const int B    = in_sizes[0] / DIN;
    const int DOUT = in_sizes[6];

    __half *xhi, *wih, *wrh, *woh, *hbuf0;
    float *xproj, *y, *v, *z, *invsig;
    int* cnt;
    cudaGetSymbolAddress((void**)&xhi, g_xhi);
    cudaGetSymbolAddress((void**)&wih, g_wih);
    cudaGetSymbolAddress((void**)&wrh, g_wrh);
    cudaGetSymbolAddress((void**)&woh, g_woh);
    cudaGetSymbolAddress((void**)&hbuf0, g_h);
    cudaGetSymbolAddress((void**)&xproj, g_xproj);
    cudaGetSymbolAddress((void**)&y, g_y); cudaGetSymbolAddress((void**)&v, g_v);
    cudaGetSymbolAddress((void**)&z, g_z); cudaGetSymbolAddress((void**)&invsig, g_invsig);
    cudaGetSymbolAddress((void**)&cnt, g_cnt);

    __half* hb0 = hbuf0;
    __half* hb1 = hbuf0 + (long)B_DIM * H_DIM;

    constexpr int SMEM_P = 3 * 2 * 16384;   // 96KB for all GEMM kernels
    cudaFuncSetAttribute(step_persistent, cudaFuncAttributeMaxDynamicSharedMemorySize, SMEM_P);
    cudaFuncSetAttribute(mma_gemm_p,      cudaFuncAttributeMaxDynamicSharedMemorySize, SMEM_P);

    // merged prologue: 6 launches
    zero_all<<<(3 * H_DIM + 255) / 256, 256>>>(y, 3 * H_DIM, cnt, NSTEPS * 32);
    colmv_all<<<dim3((H_DIM + 127) / 128, 8, 3), 128>>>(W_in, u_in, W_rec, u_rec,
                                                        W_out, u_out, y, DIN, H, DOUT);
    normalize_all<<<3, 256>>>(y, v, DIN, H);
    rowmv_all<<<dim3((H_DIM + 7) / 8, 3), 256>>>(W_in, W_rec, W_out, v, z, DIN, H, DOUT);
    sigma_all<<<3, 256>>>(z, invsig, H, DOUT);
    {
        long nx = (long)B * DIN, nwi = (long)H * DIN, nwr = (long)H * H, nwo = (long)DOUT * H;
        long tot = nx + nwi + nwr + nwo;
        split_all<<<(int)((tot + 255) / 256), 256>>>(x, W_in, W_rec, W_out, nx, nwi, nwr, nwo);
    }

    // x_proj = x @ (W_in/s)^T + b_in   (single-MMA plain fp16)
    mma_gemm_p<<<dim3(H / 128, B / 128), 256, SMEM_P>>>(
        xhi, wih, b_in, invsig + 0, DIN, H, xproj);

    // persistent: h0 init + steps 1..29
    step_persistent<<<dim3(H / 128, B / 128), 256, SMEM_P>>>(
        hb0, hb1, wrh, b_rec, invsig + 1, xproj, steps, cnt);

    // out = h @ (W_out/s)^T + b_out   (single-MMA); final h in hb1 (NSTEPS-1 odd)
    mma_gemm_p<<<dim3(DOUT / 128, B / 128), 256, SMEM_P>>>(
        hb1, woh, b_out, invsig + 2, H, DOUT, (float*)d_out);
}